// round 1
// baseline (speedup 1.0000x reference)
#include <cuda_runtime.h>
#include <math.h>

#define BB   64
#define PP   256
#define DV   1024
#define DT   768
#define SS   512
#define NSEG 32
#define PPT  8

// ---------------- scratch (static device globals; no allocation) ----------------
__device__ float g_A[BB * NSEG * DV];     // segment means of LN(vis)   [2048,1024]  8 MB
__device__ float g_segm[BB * NSEG * DT];  // projected segment means    [2048, 768]  6 MB
__device__ int   g_rank[BB * SS];         // placeholder rank or -1
__device__ float g_nrm[BB * DT];          // normalized pooled
__device__ float g_sim[BB * BB];          // similarity matrix

// ---------------- f32x2 packed helpers (Blackwell FFMA2 via PTX) ----------------
__device__ __forceinline__ unsigned long long pack2(float lo, float hi) {
    unsigned long long v;
    asm("mov.b64 %0, {%1, %2};" : "=l"(v) : "f"(lo), "f"(hi));
    return v;
}
__device__ __forceinline__ void fma2(unsigned long long& d, unsigned long long a, unsigned long long b) {
    asm("fma.rn.f32x2 %0, %1, %2, %0;" : "+l"(d) : "l"(a), "l"(b));
}
__device__ __forceinline__ float2 unpack2(unsigned long long v) {
    float2 r;
    asm("mov.b64 {%0, %1}, %2;" : "=f"(r.x), "=f"(r.y) : "l"(v));
    return r;
}

// ---------------- K1: LayerNorm + segment mean --------------------------------
// One block per segment (2048 blocks, 256 threads). Each thread owns 4 dims
// (float4) across all 8 patches of the segment; accumulates normalized values
// in registers and writes the segment MEAN (so the GEMM directly yields seg_means).
__global__ void k_ln_seg(const float* __restrict__ vis,
                         const float* __restrict__ gamma,
                         const float* __restrict__ beta) {
    int seg = blockIdx.x;
    int t = threadIdx.x;
    __shared__ float red[16];
    __shared__ float s_mu, s_ri;

    float4 g4 = *(const float4*)(gamma + 4 * t);
    float4 b4 = *(const float4*)(beta + 4 * t);
    float a0 = 0.f, a1 = 0.f, a2 = 0.f, a3 = 0.f;
    const float* base = vis + (size_t)seg * PPT * DV;

    for (int p = 0; p < PPT; p++) {
        float4 x = *(const float4*)(base + (size_t)p * DV + 4 * t);
        float s = x.x + x.y + x.z + x.w;
        float q = x.x * x.x + x.y * x.y + x.z * x.z + x.w * x.w;
        #pragma unroll
        for (int o = 16; o > 0; o >>= 1) {
            s += __shfl_down_sync(0xffffffffu, s, o);
            q += __shfl_down_sync(0xffffffffu, q, o);
        }
        int w = t >> 5;
        if ((t & 31) == 0) { red[w] = s; red[8 + w] = q; }
        __syncthreads();
        if (t == 0) {
            float ss = 0.f, qq = 0.f;
            #pragma unroll
            for (int i = 0; i < 8; i++) { ss += red[i]; qq += red[8 + i]; }
            float mu = ss * (1.0f / DV);
            float var = qq * (1.0f / DV) - mu * mu;
            s_mu = mu;
            s_ri = rsqrtf(var + 1e-5f);
        }
        __syncthreads();
        float mu = s_mu, ri = s_ri;
        a0 += (x.x - mu) * ri * g4.x + b4.x;
        a1 += (x.y - mu) * ri * g4.y + b4.y;
        a2 += (x.z - mu) * ri * g4.z + b4.z;
        a3 += (x.w - mu) * ri * g4.w + b4.w;
        __syncthreads();
    }
    float4 o;
    o.x = a0 * (1.0f / PPT); o.y = a1 * (1.0f / PPT);
    o.z = a2 * (1.0f / PPT); o.w = a3 * (1.0f / PPT);
    *(float4*)(g_A + (size_t)seg * DV + 4 * t) = o;
}

// ---------------- K2: fp32 GEMM with packed f32x2 FFMA ------------------------
// C[2048,768] = g_A[2048,1024] @ W[1024,768] + b_proj  ->  g_segm
// 64x64 tile, BK=16, 256 threads, 4x4 micro-tile, accumulators as f32x2 pairs.
__global__ void k_gemm(const float* __restrict__ Wp, const float* __restrict__ bp) {
    __shared__ float As[16][68];   // padded: conflict-free scatter stores
    __shared__ float Bs[16][64];

    int t = threadIdx.x;
    int tx = t & 15, ty = t >> 4;
    int br = blockIdx.x;           // 0..31
    int bc = blockIdx.y;           // 0..11

    unsigned long long acc[4][2];
    #pragma unroll
    for (int i = 0; i < 4; i++) { acc[i][0] = 0ull; acc[i][1] = 0ull; }

    int lr = t >> 2;               // A row within tile (0..63)
    int lc = t & 3;                // k-chunk (0..3)
    const float* Aptr = g_A + ((size_t)(br * 64 + lr)) * DV + lc * 4;
    int lk = t >> 4;               // W row within tile (0..15)
    int ln = t & 15;
    const float* Wptr = Wp + (size_t)lk * DT + bc * 64 + ln * 4;

    for (int kb = 0; kb < DV / 16; kb++) {
        float4 av = *(const float4*)(Aptr + kb * 16);
        As[lc * 4 + 0][lr] = av.x;
        As[lc * 4 + 1][lr] = av.y;
        As[lc * 4 + 2][lr] = av.z;
        As[lc * 4 + 3][lr] = av.w;
        float4 wv = *(const float4*)(Wptr + (size_t)kb * 16 * DT);
        *(float4*)&Bs[lk][ln * 4] = wv;
        __syncthreads();
        #pragma unroll
        for (int k = 0; k < 16; k++) {
            unsigned long long b01 = *(const unsigned long long*)&Bs[k][tx * 4];
            unsigned long long b23 = *(const unsigned long long*)&Bs[k][tx * 4 + 2];
            #pragma unroll
            for (int i = 0; i < 4; i++) {
                float a = As[k][ty * 4 + i];
                unsigned long long aa = pack2(a, a);
                fma2(acc[i][0], aa, b01);
                fma2(acc[i][1], aa, b23);
            }
        }
        __syncthreads();
    }

    float4 bias = *(const float4*)(bp + bc * 64 + tx * 4);
    #pragma unroll
    for (int i = 0; i < 4; i++) {
        float2 lo = unpack2(acc[i][0]);
        float2 hi = unpack2(acc[i][1]);
        float4 o;
        o.x = lo.x + bias.x; o.y = lo.y + bias.y;
        o.z = hi.x + bias.z; o.w = hi.y + bias.w;
        *(float4*)&g_segm[(size_t)(br * 64 + ty * 4 + i) * DT + bc * 64 + tx * 4] = o;
    }
}

// ---------------- K3a: per-row placeholder rank (serial scan) ------------------
__global__ void k_rank(const int* __restrict__ ids, const int* __restrict__ php) {
    int b = threadIdx.x;           // 64 threads, 1 block
    int ph = *php;
    int c = 0;
    const int* row = ids + b * SS;
    int* orow = g_rank + b * SS;
    for (int s = 0; s < SS; s++) {
        int id = row[s];
        if (id == ph) { orow[s] = c; c++; }
        else          { orow[s] = -1; }
    }
}

// ---------------- K3b: text_emb assembly (gather/copy) -------------------------
// One block per (b,s): 192 threads x float4 = 768 floats.
__global__ void k_emb(const int* __restrict__ ids, const float* __restrict__ wte,
                      float* __restrict__ out) {
    int bs = blockIdx.x;
    int r = g_rank[bs];
    const float4* src;
    if (r >= 0 && r < NSEG) {
        int b = bs >> 9;
        src = (const float4*)(g_segm + (size_t)(b * NSEG + r) * DT);
    } else {
        int id = ids[bs];
        src = (const float4*)(wte + (size_t)id * DT);
    }
    float4* dst = (float4*)(out + (size_t)bs * DT);
    dst[threadIdx.x] = src[threadIdx.x];
}

// ---------------- K4a: pooled mean + L2 normalize ------------------------------
__global__ void k_pool() {
    int b = blockIdx.x;
    int t = threadIdx.x;           // 192 threads, 4 dims each
    __shared__ float red[6];
    __shared__ float s_inv;
    float4 acc = make_float4(0.f, 0.f, 0.f, 0.f);
    const float* base = g_segm + (size_t)b * NSEG * DT;
    for (int s = 0; s < NSEG; s++) {
        float4 v = *(const float4*)(base + (size_t)s * DT + 4 * t);
        acc.x += v.x; acc.y += v.y; acc.z += v.z; acc.w += v.w;
    }
    acc.x *= (1.0f / NSEG); acc.y *= (1.0f / NSEG);
    acc.z *= (1.0f / NSEG); acc.w *= (1.0f / NSEG);
    float q = acc.x * acc.x + acc.y * acc.y + acc.z * acc.z + acc.w * acc.w;
    #pragma unroll
    for (int o = 16; o > 0; o >>= 1) q += __shfl_down_sync(0xffffffffu, q, o);
    int w = t >> 5;
    if ((t & 31) == 0) red[w] = q;
    __syncthreads();
    if (t == 0) {
        float s = 0.f;
        #pragma unroll
        for (int i = 0; i < 6; i++) s += red[i];
        s_inv = rsqrtf(s);
    }
    __syncthreads();
    float inv = s_inv;
    float4 o;
    o.x = acc.x * inv; o.y = acc.y * inv; o.z = acc.z * inv; o.w = acc.w * inv;
    *(float4*)(g_nrm + (size_t)b * DT + 4 * t) = o;
}

// ---------------- K4b: sim = nrm @ nrm^T / TEMP --------------------------------
__global__ void k_sim() {
    int i = blockIdx.x;
    int t = threadIdx.x;           // 256 threads = 8 warps
    int w = t >> 5, lane = t & 31;
    const float* a = g_nrm + (size_t)i * DT;
    for (int j = w; j < BB; j += 8) {
        const float* bv = g_nrm + (size_t)j * DT;
        float d = 0.f;
        for (int k = lane; k < DT; k += 32) d += a[k] * bv[k];
        #pragma unroll
        for (int o = 16; o > 0; o >>= 1) d += __shfl_down_sync(0xffffffffu, d, o);
        if (lane == 0) g_sim[i * BB + j] = d / 0.07f;
    }
}

// ---------------- K4c: symmetric CE loss ---------------------------------------
__global__ void k_loss(float* __restrict__ out, int out_size) {
    int i = threadIdx.x;           // 64 threads
    __shared__ float sh[2];
    // row log-softmax at diagonal
    float m = -1e30f;
    for (int j = 0; j < BB; j++) m = fmaxf(m, g_sim[i * BB + j]);
    float se = 0.f;
    for (int j = 0; j < BB; j++) se += expf(g_sim[i * BB + j] - m);
    float lr = g_sim[i * BB + i] - (m + logf(se));
    // column log-softmax at diagonal
    float m2 = -1e30f;
    for (int j = 0; j < BB; j++) m2 = fmaxf(m2, g_sim[j * BB + i]);
    float se2 = 0.f;
    for (int j = 0; j < BB; j++) se2 += expf(g_sim[j * BB + i] - m2);
    float lc = g_sim[i * BB + i] - (m2 + logf(se2));

    float v = lr + lc;
    #pragma unroll
    for (int o = 16; o > 0; o >>= 1) v += __shfl_down_sync(0xffffffffu, v, o);
    int w = i >> 5;
    if ((i & 31) == 0) sh[w] = v;
    __syncthreads();
    if (i == 0) out[out_size - 1] = -(sh[0] + sh[1]) / (2.0f * BB);
}

// ---------------- launch --------------------------------------------------------
extern "C" void kernel_launch(void* const* d_in, const int* in_sizes, int n_in,
                              void* d_out, int out_size) {
    const float* vis   = (const float*)d_in[0];
    const float* gamma = (const float*)d_in[1];
    const float* beta  = (const float*)d_in[2];
    const float* Wp    = (const float*)d_in[3];
    const float* bp    = (const float*)d_in[4];
    const float* wte   = (const float*)d_in[5];
    const int*   ids   = (const int*)d_in[6];
    const int*   php   = (const int*)d_in[7];
    float* out = (float*)d_out;

    k_ln_seg<<<BB * NSEG, 256>>>(vis, gamma, beta);
    k_gemm<<<dim3(32, 12), 256>>>(Wp, bp);
    k_rank<<<1, 64>>>(ids, php);
    k_emb<<<BB * SS, 192>>>(ids, wte, out);
    k_pool<<<BB, 192>>>();
    k_sim<<<BB, 256>>>();
    k_loss<<<1, 64>>>(out, out_size);
}

// round 3
// speedup vs baseline: 1.1558x; 1.1558x over previous
#include <cuda_runtime.h>
#include <math.h>

#define BB   64
#define PP   256
#define DV   1024
#define DT   768
#define SS   512
#define NSEG 32
#define PPT  8

// ---------------- scratch (static device globals; no allocation) ----------------
__device__ float g_A[BB * NSEG * DV];     // segment means of LN(vis)   [2048,1024]
__device__ float g_segm[BB * NSEG * DT];  // projected segment means    [2048, 768]
__device__ int   g_rank[BB * SS];         // placeholder rank or -1
__device__ float g_nrm[BB * DT];          // normalized pooled
__device__ float g_sim[BB * BB];          // similarity matrix

// ---------------- f32x2 packed helpers (Blackwell FFMA2 via PTX) ----------------
__device__ __forceinline__ void fma2(unsigned long long& d, unsigned long long a, unsigned long long b) {
    asm("fma.rn.f32x2 %0, %1, %2, %0;" : "+l"(d) : "l"(a), "l"(b));
}
__device__ __forceinline__ float2 unpack2(unsigned long long v) {
    float2 r;
    asm("mov.b64 {%0, %1}, %2;" : "=f"(r.x), "=f"(r.y) : "l"(v));
    return r;
}

// ---------------- K1: LayerNorm + segment mean --------------------------------
// One block per segment (2048 blocks, 256 threads). All 8 patches held in regs;
// single batched reduction pass -> only 2 __syncthreads per block.
__global__ void k_ln_seg(const float* __restrict__ vis,
                         const float* __restrict__ gamma,
                         const float* __restrict__ beta) {
    int seg = blockIdx.x;
    int t = threadIdx.x;
    int lane = t & 31, w = t >> 5;

    __shared__ float rs[PPT][8], rq[PPT][8];
    __shared__ float s_mu[PPT], s_ri[PPT];

    const float* base = vis + (size_t)seg * PPT * DV;
    float4 x[PPT];
    float s[PPT], q[PPT];
    #pragma unroll
    for (int p = 0; p < PPT; p++) {
        x[p] = *(const float4*)(base + (size_t)p * DV + 4 * t);
        s[p] = x[p].x + x[p].y + x[p].z + x[p].w;
        q[p] = x[p].x * x[p].x + x[p].y * x[p].y + x[p].z * x[p].z + x[p].w * x[p].w;
    }
    #pragma unroll
    for (int p = 0; p < PPT; p++) {
        #pragma unroll
        for (int o = 16; o > 0; o >>= 1) {
            s[p] += __shfl_down_sync(0xffffffffu, s[p], o);
            q[p] += __shfl_down_sync(0xffffffffu, q[p], o);
        }
        if (lane == 0) { rs[p][w] = s[p]; rq[p][w] = q[p]; }
    }
    __syncthreads();
    if (t < PPT) {
        float ss = 0.f, qq = 0.f;
        #pragma unroll
        for (int i = 0; i < 8; i++) { ss += rs[t][i]; qq += rq[t][i]; }
        float mu = ss * (1.0f / DV);
        float var = qq * (1.0f / DV) - mu * mu;
        s_mu[t] = mu;
        s_ri[t] = rsqrtf(var + 1e-5f);
    }
    __syncthreads();

    float4 g4 = *(const float4*)(gamma + 4 * t);
    float4 b4 = *(const float4*)(beta + 4 * t);
    float a0 = 0.f, a1 = 0.f, a2 = 0.f, a3 = 0.f;
    #pragma unroll
    for (int p = 0; p < PPT; p++) {
        float mu = s_mu[p], ri = s_ri[p];
        a0 += (x[p].x - mu) * ri * g4.x + b4.x;
        a1 += (x[p].y - mu) * ri * g4.y + b4.y;
        a2 += (x[p].z - mu) * ri * g4.z + b4.z;
        a3 += (x[p].w - mu) * ri * g4.w + b4.w;
    }
    float4 o;
    o.x = a0 * (1.0f / PPT); o.y = a1 * (1.0f / PPT);
    o.z = a2 * (1.0f / PPT); o.w = a3 * (1.0f / PPT);
    *(float4*)(g_A + (size_t)seg * DV + 4 * t) = o;
}

// ---------------- K2: fp32 GEMM with packed f32x2 FFMA ------------------------
// C[2048,768] = g_A[2048,1024] @ W[1024,768] + b_proj  ->  g_segm
// 128x64 tile, BK=16, 256 threads, 8Mx4N micro-tile. f32x2 lanes span M-pairs
// so A-pairs load directly from smem; B stored DUPLICATED ([n,n] pairs) with a
// bank skew so B-pairs also load directly -> zero packing movs in inner loop.
__global__ void __launch_bounds__(256, 2) k_gemm(const float* __restrict__ Wp,
                                                 const float* __restrict__ bp) {
    __shared__ float As[16][132];   // k-major A tile, 528B rows (16B aligned)
    __shared__ float Bs2[16][144];  // duplicated B pairs, skewed

    int t = threadIdx.x;
    int tx = t & 15, ty = t >> 4;
    int br = blockIdx.x;            // 0..15  (M tiles of 128)
    int bc = blockIdx.y;            // 0..11  (N tiles of 64)

    unsigned long long acc[4][4];
    #pragma unroll
    for (int i = 0; i < 4; i++)
        #pragma unroll
        for (int j = 0; j < 4; j++) acc[i][j] = 0ull;

    // A global-load mapping: 128 rows x 16 k per tile; thread: row t>>1, k-half t&1
    int lr = t >> 1, lc = t & 1;
    const float* Ap = g_A + (size_t)(br * 128 + lr) * DV + lc * 8;
    // B global-load mapping: 16 k-rows x 64 cols; thread: k-row t>>4, col-group t&15
    int lk = t >> 4, ln = t & 15;
    const float* Wpp = Wp + (size_t)lk * DT + bc * 64 + ln * 4;
    int boff_w = ln * 8 + (ln >> 2) * 4;        // skewed duplicated-B offset (writer)
    int boff_r = tx * 8 + (tx >> 2) * 4;        // (reader)

    float4 a0 = *(const float4*)(Ap);
    float4 a1 = *(const float4*)(Ap + 4);
    float4 wv = *(const float4*)(Wpp);

    for (int kb = 0; kb < DV / 16; kb++) {
        As[lc * 8 + 0][lr] = a0.x;  As[lc * 8 + 1][lr] = a0.y;
        As[lc * 8 + 2][lr] = a0.z;  As[lc * 8 + 3][lr] = a0.w;
        As[lc * 8 + 4][lr] = a1.x;  As[lc * 8 + 5][lr] = a1.y;
        As[lc * 8 + 6][lr] = a1.z;  As[lc * 8 + 7][lr] = a1.w;
        float4 d0 = make_float4(wv.x, wv.x, wv.y, wv.y);
        float4 d1 = make_float4(wv.z, wv.z, wv.w, wv.w);
        *(float4*)&Bs2[lk][boff_w]     = d0;
        *(float4*)&Bs2[lk][boff_w + 4] = d1;
        __syncthreads();

        if (kb < DV / 16 - 1) {
            a0 = *(const float4*)(Ap + (kb + 1) * 16);
            a1 = *(const float4*)(Ap + (kb + 1) * 16 + 4);
            wv = *(const float4*)(Wpp + (size_t)(kb + 1) * 16 * DT);
        }

        #pragma unroll
        for (int k = 0; k < 16; k++) {
            ulonglong2 A01 = *(const ulonglong2*)&As[k][ty * 8];
            ulonglong2 A23 = *(const ulonglong2*)&As[k][ty * 8 + 4];
            ulonglong2 B01 = *(const ulonglong2*)&Bs2[k][boff_r];
            ulonglong2 B23 = *(const ulonglong2*)&Bs2[k][boff_r + 4];
            fma2(acc[0][0], A01.x, B01.x); fma2(acc[0][1], A01.x, B01.y);
            fma2(acc[0][2], A01.x, B23.x); fma2(acc[0][3], A01.x, B23.y);
            fma2(acc[1][0], A01.y, B01.x); fma2(acc[1][1], A01.y, B01.y);
            fma2(acc[1][2], A01.y, B23.x); fma2(acc[1][3], A01.y, B23.y);
            fma2(acc[2][0], A23.x, B01.x); fma2(acc[2][1], A23.x, B01.y);
            fma2(acc[2][2], A23.x, B23.x); fma2(acc[2][3], A23.x, B23.y);
            fma2(acc[3][0], A23.y, B01.x); fma2(acc[3][1], A23.y, B01.y);
            fma2(acc[3][2], A23.y, B23.x); fma2(acc[3][3], A23.y, B23.y);
        }
        __syncthreads();
    }

    float4 bias = *(const float4*)(bp + bc * 64 + tx * 4);
    #pragma unroll
    for (int mp = 0; mp < 4; mp++) {
        float2 v0 = unpack2(acc[mp][0]);
        float2 v1 = unpack2(acc[mp][1]);
        float2 v2 = unpack2(acc[mp][2]);
        float2 v3 = unpack2(acc[mp][3]);
        int m0 = br * 128 + ty * 8 + 2 * mp;
        float* dst0 = g_segm + (size_t)m0 * DT + bc * 64 + tx * 4;
        float4 o0, o1;
        o0.x = v0.x + bias.x; o0.y = v1.x + bias.y; o0.z = v2.x + bias.z; o0.w = v3.x + bias.w;
        o1.x = v0.y + bias.x; o1.y = v1.y + bias.y; o1.z = v2.y + bias.z; o1.w = v3.y + bias.w;
        *(float4*)dst0        = o0;
        *(float4*)(dst0 + DT) = o1;
    }
}

// ---------------- K3a: per-row placeholder rank (warp ballot scan) --------------
__global__ void k_rank(const int* __restrict__ ids, const int* __restrict__ php) {
    int b = blockIdx.x;            // 64 blocks, 32 threads
    int lane = threadIdx.x;
    int ph = *php;
    const int* row = ids + b * SS;
    int* orow = g_rank + b * SS;
    int base = 0;
    unsigned below = (1u << lane) - 1u;
    #pragma unroll
    for (int c = 0; c < SS / 32; c++) {
        int id = row[c * 32 + lane];
        unsigned m = __ballot_sync(0xffffffffu, id == ph);
        int r = base + __popc(m & below);
        orow[c * 32 + lane] = (id == ph) ? r : -1;
        base += __popc(m);
    }
}

// ---------------- K3b: text_emb assembly (gather/copy, 4 rows/block) ------------
__global__ void k_emb(const int* __restrict__ ids, const float* __restrict__ wte,
                      float* __restrict__ out) {
    int base = blockIdx.x * 4;
    int tid = threadIdx.x;         // 192 threads x float4 = 768 floats/row
    const float4* src[4];
    #pragma unroll
    for (int r = 0; r < 4; r++) {
        int bs = base + r;
        int rk = g_rank[bs];
        if (rk >= 0 && rk < NSEG) {
            int b = bs >> 9;
            src[r] = (const float4*)(g_segm + (size_t)(b * NSEG + rk) * DT);
        } else {
            int id = ids[bs];
            src[r] = (const float4*)(wte + (size_t)id * DT);
        }
    }
    float4 v[4];
    #pragma unroll
    for (int r = 0; r < 4; r++) v[r] = src[r][tid];
    #pragma unroll
    for (int r = 0; r < 4; r++)
        *(float4*)(out + (size_t)(base + r) * DT + 4 * tid) = v[r];
}

// ---------------- K4a: pooled mean + L2 normalize ------------------------------
__global__ void k_pool() {
    int b = blockIdx.x;
    int t = threadIdx.x;           // 192 threads, 4 dims each
    __shared__ float red[6];
    __shared__ float s_inv;
    float4 acc = make_float4(0.f, 0.f, 0.f, 0.f);
    const float* base = g_segm + (size_t)b * NSEG * DT;
    for (int s = 0; s < NSEG; s++) {
        float4 v = *(const float4*)(base + (size_t)s * DT + 4 * t);
        acc.x += v.x; acc.y += v.y; acc.z += v.z; acc.w += v.w;
    }
    acc.x *= (1.0f / NSEG); acc.y *= (1.0f / NSEG);
    acc.z *= (1.0f / NSEG); acc.w *= (1.0f / NSEG);
    float q = acc.x * acc.x + acc.y * acc.y + acc.z * acc.z + acc.w * acc.w;
    #pragma unroll
    for (int o = 16; o > 0; o >>= 1) q += __shfl_down_sync(0xffffffffu, q, o);
    int w = t >> 5;
    if ((t & 31) == 0) red[w] = q;
    __syncthreads();
    if (t == 0) {
        float s = 0.f;
        #pragma unroll
        for (int i = 0; i < 6; i++) s += red[i];
        s_inv = rsqrtf(s);
    }
    __syncthreads();
    float inv = s_inv;
    float4 o;
    o.x = acc.x * inv; o.y = acc.y * inv; o.z = acc.z * inv; o.w = acc.w * inv;
    *(float4*)(g_nrm + (size_t)b * DT + 4 * t) = o;
}

// ---------------- K4b: sim = nrm @ nrm^T / TEMP --------------------------------
__global__ void k_sim() {
    int i = blockIdx.x;
    int t = threadIdx.x;           // 256 threads = 8 warps
    int w = t >> 5, lane = t & 31;
    const float* a = g_nrm + (size_t)i * DT;
    for (int j = w; j < BB; j += 8) {
        const float* bv = g_nrm + (size_t)j * DT;
        float d = 0.f;
        for (int k = lane; k < DT; k += 32) d += a[k] * bv[k];
        #pragma unroll
        for (int o = 16; o > 0; o >>= 1) d += __shfl_down_sync(0xffffffffu, d, o);
        if (lane == 0) g_sim[i * BB + j] = d / 0.07f;
    }
}

// ---------------- K4c: CE loss (sim symmetric -> ce_col == ce_row) -------------
__global__ void k_loss(float* __restrict__ out, int out_size) {
    int i = threadIdx.x;           // 64 threads
    __shared__ float sh[2];
    float m = -1e30f;
    for (int j = 0; j < BB; j++) m = fmaxf(m, g_sim[i * BB + j]);
    float se = 0.f;
    for (int j = 0; j < BB; j++) se += expf(g_sim[i * BB + j] - m);
    float lr = g_sim[i * BB + i] - (m + logf(se));

    float v = lr;
    #pragma unroll
    for (int o = 16; o > 0; o >>= 1) v += __shfl_down_sync(0xffffffffu, v, o);
    int w = i >> 5;
    if ((i & 31) == 0) sh[w] = v;
    __syncthreads();
    if (i == 0) out[out_size - 1] = -(sh[0] + sh[1]) / (float)BB;
}

// ---------------- launch --------------------------------------------------------
extern "C" void kernel_launch(void* const* d_in, const int* in_sizes, int n_in,
                              void* d_out, int out_size) {
    const float* vis   = (const float*)d_in[0];
    const float* gamma = (const float*)d_in[1];
    const float* beta  = (const float*)d_in[2];
    const float* Wp    = (const float*)d_in[3];
    const float* bp    = (const float*)d_in[4];
    const float* wte   = (const float*)d_in[5];
    const int*   ids   = (const int*)d_in[6];
    const int*   php   = (const int*)d_in[7];
    float* out = (float*)d_out;

    k_ln_seg<<<BB * NSEG, 256>>>(vis, gamma, beta);
    k_gemm<<<dim3(16, 12), 256>>>(Wp, bp);
    k_rank<<<BB, 32>>>(ids, php);
    k_emb<<<(BB * SS) / 4, 192>>>(ids, wte, out);
    k_pool<<<BB, 192>>>();
    k_sim<<<BB, 256>>>();
    k_loss<<<1, 64>>>(out, out_size);
}

// round 5
// speedup vs baseline: 2.0876x; 1.8061x over previous
#include <cuda_runtime.h>
#include <cuda_bf16.h>
#include <math.h>

#define BB   64
#define PP   256
#define DV   1024
#define DT   768
#define SS   512
#define NSEG 32
#define PPT  8

#define MROWS 2048            // = BB*NSEG
#define TM    128             // GEMM M tile
#define TN    96              // GEMM N tile

// ---------------- scratch (static device globals; no allocation) ----------------
__device__ unsigned short g_Ah[MROWS * DV];   // bf16 hi split of segment means (K-major)
__device__ unsigned short g_Am[MROWS * DV];   // bf16 mid split
__device__ unsigned short g_Wh[DT * DV];      // bf16 hi split of W^T  [N=768][K=1024]
__device__ unsigned short g_Wm[DT * DV];      // bf16 mid split
__device__ float g_segm[MROWS * DT];          // projected segment means [2048,768]
__device__ int   g_rank[BB * SS];
__device__ float g_nrm[BB * DT];
__device__ float g_sim[BB * BB];

// ---------------- PTX helpers (baseline PTX only: sm_80-class ops) --------------
__device__ __forceinline__ unsigned smem_u32(const void* p) {
    unsigned a;
    asm("{ .reg .u64 t; cvta.to.shared.u64 t, %1; cvt.u32.u64 %0, t; }" : "=r"(a) : "l"(p));
    return a;
}
__device__ __forceinline__ void cp16(unsigned saddr, const void* gptr) {
    asm volatile("cp.async.cg.shared.global [%0], [%1], 16;" :: "r"(saddr), "l"(gptr) : "memory");
}
__device__ __forceinline__ void cp_commit() {
    asm volatile("cp.async.commit_group;" ::: "memory");
}
__device__ __forceinline__ void cp_wait1() {
    asm volatile("cp.async.wait_group 1;" ::: "memory");
}
__device__ __forceinline__ void cp_wait0() {
    asm volatile("cp.async.wait_group 0;" ::: "memory");
}
__device__ __forceinline__ void ldsm4(unsigned* r, unsigned addr) {
    asm volatile("ldmatrix.sync.aligned.m8n8.x4.shared.b16 {%0,%1,%2,%3}, [%4];"
                 : "=r"(r[0]), "=r"(r[1]), "=r"(r[2]), "=r"(r[3]) : "r"(addr));
}
__device__ __forceinline__ void mma16816(float* c, const unsigned* a, const unsigned* b) {
    asm volatile(
        "mma.sync.aligned.m16n8k16.row.col.f32.bf16.bf16.f32 "
        "{%0,%1,%2,%3}, {%4,%5,%6,%7}, {%8,%9}, {%0,%1,%2,%3};"
        : "+f"(c[0]), "+f"(c[1]), "+f"(c[2]), "+f"(c[3])
        : "r"(a[0]), "r"(a[1]), "r"(a[2]), "r"(a[3]), "r"(b[0]), "r"(b[1]));
}

// 2-way bf16 split (hi exact-rounded, mid = residual)
__device__ __forceinline__ void split2(float v, unsigned short& h, unsigned short& m) {
    __nv_bfloat16 bh = __float2bfloat16(v);
    float r1 = v - __bfloat162float(bh);
    __nv_bfloat16 bm = __float2bfloat16(r1);
    h = __bfloat16_as_ushort(bh);
    m = __bfloat16_as_ushort(bm);
}

// ---------------- K1: LayerNorm + segment mean -> bf16 splits -------------------
__global__ void k_ln_seg(const float* __restrict__ vis,
                         const float* __restrict__ gamma,
                         const float* __restrict__ beta) {
    int seg = blockIdx.x;
    int t = threadIdx.x;
    int lane = t & 31, w = t >> 5;

    __shared__ float rs[PPT][8], rq[PPT][8];
    __shared__ float s_mu[PPT], s_ri[PPT];

    const float* base = vis + (size_t)seg * PPT * DV;
    float4 x[PPT];
    float s[PPT], q[PPT];
    #pragma unroll
    for (int p = 0; p < PPT; p++) {
        x[p] = *(const float4*)(base + (size_t)p * DV + 4 * t);
        s[p] = x[p].x + x[p].y + x[p].z + x[p].w;
        q[p] = x[p].x * x[p].x + x[p].y * x[p].y + x[p].z * x[p].z + x[p].w * x[p].w;
    }
    #pragma unroll
    for (int p = 0; p < PPT; p++) {
        #pragma unroll
        for (int o = 16; o > 0; o >>= 1) {
            s[p] += __shfl_down_sync(0xffffffffu, s[p], o);
            q[p] += __shfl_down_sync(0xffffffffu, q[p], o);
        }
        if (lane == 0) { rs[p][w] = s[p]; rq[p][w] = q[p]; }
    }
    __syncthreads();
    if (t < PPT) {
        float ss = 0.f, qq = 0.f;
        #pragma unroll
        for (int i = 0; i < 8; i++) { ss += rs[t][i]; qq += rq[t][i]; }
        float mu = ss * (1.0f / DV);
        float var = qq * (1.0f / DV) - mu * mu;
        s_mu[t] = mu;
        s_ri[t] = rsqrtf(var + 1e-5f);
    }
    __syncthreads();

    float4 g4 = *(const float4*)(gamma + 4 * t);
    float4 b4 = *(const float4*)(beta + 4 * t);
    float a0 = 0.f, a1 = 0.f, a2 = 0.f, a3 = 0.f;
    #pragma unroll
    for (int p = 0; p < PPT; p++) {
        float mu = s_mu[p], ri = s_ri[p];
        a0 += (x[p].x - mu) * ri * g4.x + b4.x;
        a1 += (x[p].y - mu) * ri * g4.y + b4.y;
        a2 += (x[p].z - mu) * ri * g4.z + b4.z;
        a3 += (x[p].w - mu) * ri * g4.w + b4.w;
    }
    float v[4] = { a0 * (1.0f / PPT), a1 * (1.0f / PPT), a2 * (1.0f / PPT), a3 * (1.0f / PPT) };
    unsigned short h[4], m[4];
    #pragma unroll
    for (int i = 0; i < 4; i++) split2(v[i], h[i], m[i]);
    size_t off = (size_t)seg * DV + 4 * t;
    uint2 ph = make_uint2((unsigned)h[0] | ((unsigned)h[1] << 16), (unsigned)h[2] | ((unsigned)h[3] << 16));
    uint2 pm = make_uint2((unsigned)m[0] | ((unsigned)m[1] << 16), (unsigned)m[2] | ((unsigned)m[3] << 16));
    *(uint2*)(g_Ah + off) = ph;
    *(uint2*)(g_Am + off) = pm;
}

// ---------------- K1b: transpose + split W [1024,768] -> W^T splits [768,1024] --
__global__ void k_wsplit(const float* __restrict__ Wp) {
    __shared__ float tile[32][33];
    int k0 = blockIdx.x * 32;       // K block
    int n0 = blockIdx.y * 32;       // N block
    int tx = threadIdx.x & 31, ty = threadIdx.x >> 5;   // 32x8
    #pragma unroll
    for (int i = 0; i < 4; i++)
        tile[ty + 8 * i][tx] = Wp[(size_t)(k0 + ty + 8 * i) * DT + n0 + tx];
    __syncthreads();
    #pragma unroll
    for (int i = 0; i < 4; i++) {
        int n = n0 + ty + 8 * i;
        int k = k0 + tx;
        float v = tile[tx][ty + 8 * i];
        unsigned short h, m;
        split2(v, h, m);
        size_t off = (size_t)n * DV + k;
        g_Wh[off] = h; g_Wm[off] = m;
    }
}

// ---------------- K2: bf16 split GEMM on mma.sync (HMMA) -----------------------
// C[2048,768] = A @ W^T + bias via 3 bf16 cross terms (hh, hm, mh).
// 128x96 tile, grid (16,8) = 128 CTAs = one wave. 256 threads, warp grid 4Mx2N
// (warp tile 32x48). K chunks of 32, cp.async double buffer.
// Smem rows padded to 40 halves (80B stride) -> ldmatrix conflict-free.

#define KPAD 40
#define A_SPLIT_B (TM * KPAD * 2)      // 10240 B
#define B_SPLIT_B (TN * KPAD * 2)      // 7680 B
#define BUF_STRIDE (2 * A_SPLIT_B + 2 * B_SPLIT_B)   // 35840 B
#define GEMM_SMEM (2 * BUF_STRIDE)                   // 71680 B

__device__ __forceinline__ void load_chunk(unsigned base, int tileM, int tileN, int c, int t) {
    #pragma unroll
    for (int s = 0; s < 2; s++) {
        const unsigned short* gA = s ? g_Am : g_Ah;
        #pragma unroll
        for (int i = 0; i < 2; i++) {
            int idx = t + 256 * i;              // 512 uint4
            int row = idx >> 2, kq = idx & 3;
            cp16(base + s * A_SPLIT_B + row * (KPAD * 2) + kq * 16,
                 gA + (size_t)(tileM * TM + row) * DV + c * 32 + kq * 8);
        }
    }
    #pragma unroll
    for (int s = 0; s < 2; s++) {
        const unsigned short* gB = s ? g_Wm : g_Wh;
        #pragma unroll
        for (int i = 0; i < 2; i++) {
            int idx = t + 256 * i;              // 384 uint4
            if (idx < (TN * 32) / 8) {
                int row = idx >> 2, kq = idx & 3;
                cp16(base + 2 * A_SPLIT_B + s * B_SPLIT_B + row * (KPAD * 2) + kq * 16,
                     gB + (size_t)(tileN * TN + row) * DV + c * 32 + kq * 8);
            }
        }
    }
}

__global__ void __launch_bounds__(256, 1) k_gemm_tc(const float* __restrict__ bp) {
    extern __shared__ __align__(16) unsigned char smem[];
    unsigned sb = smem_u32(smem);
    int t = threadIdx.x;
    int wid = t >> 5, lane = t & 31;
    int tileM = blockIdx.x, tileN = blockIdx.y;
    int warpM = (wid & 3) * 32, warpN = (wid >> 2) * 48;
    int g = lane >> 2, t4 = lane & 3;
    int l7 = lane & 7, mat = lane >> 3;

    // ldmatrix lane row/col offsets (halves)
    int aRow = (mat & 1) * 8 + l7;      // A mats: (m0-7,k0),(m8-15,k0),(m0-7,k8),(m8-15,k8)
    int aK   = (mat >> 1) * 8;
    int bRow = (mat >> 1) * 8 + l7;     // B mats: (n0-7,k0),(n0-7,k8),(n8-15,k0),(n8-15,k8)
    int bK   = (mat & 1) * 8;

    float acc[2][6][4];
    #pragma unroll
    for (int i = 0; i < 2; i++)
        #pragma unroll
        for (int j = 0; j < 6; j++)
            #pragma unroll
            for (int k = 0; k < 4; k++) acc[i][j][k] = 0.f;

    load_chunk(sb, tileM, tileN, 0, t);
    cp_commit();

    for (int c = 0; c < DV / 32; c++) {
        if (c < DV / 32 - 1) {
            load_chunk(sb + ((c + 1) & 1) * BUF_STRIDE, tileM, tileN, c + 1, t);
            cp_commit();
            cp_wait1();
        } else {
            cp_wait0();
        }
        __syncthreads();

        unsigned base = sb + (c & 1) * BUF_STRIDE;
        #pragma unroll
        for (int kk = 0; kk < 2; kk++) {
            unsigned af[2][2][4];
            #pragma unroll
            for (int s = 0; s < 2; s++)
                #pragma unroll
                for (int mt = 0; mt < 2; mt++)
                    ldsm4(af[s][mt], base + s * A_SPLIT_B +
                          ((warpM + mt * 16 + aRow) * KPAD + kk * 16 + aK) * 2);
            unsigned bf[2][6][2];
            #pragma unroll
            for (int s = 0; s < 2; s++)
                #pragma unroll
                for (int nt = 0; nt < 3; nt++) {
                    unsigned r[4];
                    ldsm4(r, base + 2 * A_SPLIT_B + s * B_SPLIT_B +
                          ((warpN + nt * 16 + bRow) * KPAD + kk * 16 + bK) * 2);
                    bf[s][nt * 2][0] = r[0]; bf[s][nt * 2][1] = r[1];
                    bf[s][nt * 2 + 1][0] = r[2]; bf[s][nt * 2 + 1][1] = r[3];
                }
            // terms: (Ah,Bh), (Ah,Bm), (Am,Bh)
            #pragma unroll
            for (int tm = 0; tm < 3; tm++) {
                const int sa = (tm == 2) ? 1 : 0;
                const int sbv = (tm == 1) ? 1 : 0;
                #pragma unroll
                for (int mt = 0; mt < 2; mt++)
                    #pragma unroll
                    for (int n = 0; n < 6; n++)
                        mma16816(acc[mt][n], af[sa][mt], bf[sbv][n]);
            }
        }
        __syncthreads();
    }

    // epilogue: C frag c0,c1 -> row g, cols 2t,2t+1; c2,c3 -> row g+8
    #pragma unroll
    for (int mt = 0; mt < 2; mt++) {
        int row0 = tileM * TM + warpM + mt * 16 + g;
        #pragma unroll
        for (int n = 0; n < 6; n++) {
            int col = tileN * TN + warpN + n * 8 + t4 * 2;
            float b0 = bp[col], b1 = bp[col + 1];
            float2 v0 = make_float2(acc[mt][n][0] + b0, acc[mt][n][1] + b1);
            float2 v1 = make_float2(acc[mt][n][2] + b0, acc[mt][n][3] + b1);
            *(float2*)(g_segm + (size_t)row0 * DT + col) = v0;
            *(float2*)(g_segm + (size_t)(row0 + 8) * DT + col) = v1;
        }
    }
}

// ---------------- K3a: per-row placeholder rank (warp ballot scan) --------------
__global__ void k_rank(const int* __restrict__ ids, const int* __restrict__ php) {
    int b = blockIdx.x;
    int lane = threadIdx.x;
    int ph = *php;
    const int* row = ids + b * SS;
    int* orow = g_rank + b * SS;
    int base = 0;
    unsigned below = (1u << lane) - 1u;
    #pragma unroll
    for (int c = 0; c < SS / 32; c++) {
        int id = row[c * 32 + lane];
        unsigned m = __ballot_sync(0xffffffffu, id == ph);
        int r = base + __popc(m & below);
        orow[c * 32 + lane] = (id == ph) ? r : -1;
        base += __popc(m);
    }
}

// ---------------- K3b: text_emb assembly (gather/copy, 8 rows/block) ------------
__global__ void k_emb(const int* __restrict__ ids, const float* __restrict__ wte,
                      float* __restrict__ out) {
    int base = blockIdx.x * 8;
    int tid = threadIdx.x;         // 192 threads x float4 = 768 floats/row
    const float4* src[8];
    #pragma unroll
    for (int r = 0; r < 8; r++) {
        int bs = base + r;
        int rk = g_rank[bs];
        if (rk >= 0 && rk < NSEG) {
            int b = bs >> 9;
            src[r] = (const float4*)(g_segm + (size_t)(b * NSEG + rk) * DT);
        } else {
            int id = ids[bs];
            src[r] = (const float4*)(wte + (size_t)id * DT);
        }
    }
    float4 v[8];
    #pragma unroll
    for (int r = 0; r < 8; r++) v[r] = src[r][tid];
    #pragma unroll
    for (int r = 0; r < 8; r++)
        *(float4*)(out + (size_t)(base + r) * DT + 4 * tid) = v[r];
}

// ---------------- K4a: pooled mean + L2 normalize ------------------------------
__global__ void k_pool() {
    int b = blockIdx.x;
    int t = threadIdx.x;
    __shared__ float red[6];
    __shared__ float s_inv;
    float4 acc = make_float4(0.f, 0.f, 0.f, 0.f);
    const float* base = g_segm + (size_t)b * NSEG * DT;
    for (int s = 0; s < NSEG; s++) {
        float4 v = *(const float4*)(base + (size_t)s * DT + 4 * t);
        acc.x += v.x; acc.y += v.y; acc.z += v.z; acc.w += v.w;
    }
    acc.x *= (1.0f / NSEG); acc.y *= (1.0f / NSEG);
    acc.z *= (1.0f / NSEG); acc.w *= (1.0f / NSEG);
    float q = acc.x * acc.x + acc.y * acc.y + acc.z * acc.z + acc.w * acc.w;
    #pragma unroll
    for (int o = 16; o > 0; o >>= 1) q += __shfl_down_sync(0xffffffffu, q, o);
    int w = t >> 5;
    if ((t & 31) == 0) red[w] = q;
    __syncthreads();
    if (t == 0) {
        float s = 0.f;
        #pragma unroll
        for (int i = 0; i < 6; i++) s += red[i];
        s_inv = rsqrtf(s);
    }
    __syncthreads();
    float inv = s_inv;
    float4 o;
    o.x = acc.x * inv; o.y = acc.y * inv; o.z = acc.z * inv; o.w = acc.w * inv;
    *(float4*)(g_nrm + (size_t)b * DT + 4 * t) = o;
}

// ---------------- K4b: sim = nrm @ nrm^T / TEMP --------------------------------
__global__ void k_sim() {
    int i = blockIdx.x;
    int t = threadIdx.x;
    int w = t >> 5, lane = t & 31;
    const float* a = g_nrm + (size_t)i * DT;
    for (int j = w; j < BB; j += 8) {
        const float* bv = g_nrm + (size_t)j * DT;
        float d = 0.f;
        for (int k = lane; k < DT; k += 32) d += a[k] * bv[k];
        #pragma unroll
        for (int o = 16; o > 0; o >>= 1) d += __shfl_down_sync(0xffffffffu, d, o);
        if (lane == 0) g_sim[i * BB + j] = d / 0.07f;
    }
}

// ---------------- K4c: CE loss (sim symmetric -> ce_col == ce_row) -------------
__global__ void k_loss(float* __restrict__ out, int out_size) {
    int i = threadIdx.x;
    __shared__ float sh[2];
    float m = -1e30f;
    for (int j = 0; j < BB; j++) m = fmaxf(m, g_sim[i * BB + j]);
    float se = 0.f;
    for (int j = 0; j < BB; j++) se += expf(g_sim[i * BB + j] - m);
    float lr = g_sim[i * BB + i] - (m + logf(se));

    float v = lr;
    #pragma unroll
    for (int o = 16; o > 0; o >>= 1) v += __shfl_down_sync(0xffffffffu, v, o);
    int w = i >> 5;
    if ((i & 31) == 0) sh[w] = v;
    __syncthreads();
    if (i == 0) out[out_size - 1] = -(sh[0] + sh[1]) / (float)BB;
}

// ---------------- launch --------------------------------------------------------
extern "C" void kernel_launch(void* const* d_in, const int* in_sizes, int n_in,
                              void* d_out, int out_size) {
    const float* vis   = (const float*)d_in[0];
    const float* gamma = (const float*)d_in[1];
    const float* beta  = (const float*)d_in[2];
    const float* Wp    = (const float*)d_in[3];
    const float* bp    = (const float*)d_in[4];
    const float* wte   = (const float*)d_in[5];
    const int*   ids   = (const int*)d_in[6];
    const int*   php   = (const int*)d_in[7];
    float* out = (float*)d_out;

    static int smem_set = 0;
    if (!smem_set) {
        cudaFuncSetAttribute(k_gemm_tc, cudaFuncAttributeMaxDynamicSharedMemorySize, GEMM_SMEM);
        smem_set = 1;
    }

    k_ln_seg<<<BB * NSEG, 256>>>(vis, gamma, beta);
    k_wsplit<<<dim3(DV / 32, DT / 32), 256>>>(Wp);
    k_gemm_tc<<<dim3(MROWS / TM, DT / TN), 256, GEMM_SMEM>>>(bp);
    k_rank<<<BB, 32>>>(ids, php);
    k_emb<<<(BB * SS) / 8, 192>>>(ids, wte, out);
    k_pool<<<BB, 192>>>();
    k_sim<<<BB, 256>>>();
    k_loss<<<1, 64>>>(out, out_size);
}

// round 6
// speedup vs baseline: 2.3131x; 1.1080x over previous
#include <cuda_runtime.h>
#include <cuda_bf16.h>
#include <math.h>

#define BB   64
#define PP   256
#define DV   1024
#define DT   768
#define SS   512
#define NSEG 32
#define PPT  8

#define MROWS 2048            // = BB*NSEG
#define TM    128             // GEMM M tile
#define TN    96              // GEMM N tile

// ---------------- scratch (static device globals; no allocation) ----------------
__device__ unsigned short g_Ah[MROWS * DV];   // bf16 hi split of segment means (K-major)
__device__ unsigned short g_Am[MROWS * DV];   // bf16 mid split
__device__ unsigned short g_Wh[DT * DV];      // bf16 hi split of W^T  [N=768][K=1024]
__device__ unsigned short g_Wm[DT * DV];      // bf16 mid split
__device__ float g_segm[MROWS * DT];          // projected segment means [2048,768]
__device__ float g_pooled[BB * DT];           // pooled (un-normalized) [64,768]
__device__ int   g_rank[BB * SS];             // placeholder rank or -1
__device__ int   g_phpos[BB * NSEG];          // position of r-th placeholder in row b
__device__ int   g_phcnt[BB];                 // per-row placeholder count
__device__ float g_sim[BB * BB];              // raw Gram matrix

// ---------------- PTX helpers (baseline PTX only: sm_80-class ops) --------------
__device__ __forceinline__ unsigned smem_u32(const void* p) {
    unsigned a;
    asm("{ .reg .u64 t; cvta.to.shared.u64 t, %1; cvt.u32.u64 %0, t; }" : "=r"(a) : "l"(p));
    return a;
}
__device__ __forceinline__ void cp16(unsigned saddr, const void* gptr) {
    asm volatile("cp.async.cg.shared.global [%0], [%1], 16;" :: "r"(saddr), "l"(gptr) : "memory");
}
__device__ __forceinline__ void cp_commit() {
    asm volatile("cp.async.commit_group;" ::: "memory");
}
__device__ __forceinline__ void cp_wait1() {
    asm volatile("cp.async.wait_group 1;" ::: "memory");
}
__device__ __forceinline__ void cp_wait0() {
    asm volatile("cp.async.wait_group 0;" ::: "memory");
}
__device__ __forceinline__ void ldsm4(unsigned* r, unsigned addr) {
    asm volatile("ldmatrix.sync.aligned.m8n8.x4.shared.b16 {%0,%1,%2,%3}, [%4];"
                 : "=r"(r[0]), "=r"(r[1]), "=r"(r[2]), "=r"(r[3]) : "r"(addr));
}
__device__ __forceinline__ void mma16816(float* c, const unsigned* a, const unsigned* b) {
    asm volatile(
        "mma.sync.aligned.m16n8k16.row.col.f32.bf16.bf16.f32 "
        "{%0,%1,%2,%3}, {%4,%5,%6,%7}, {%8,%9}, {%0,%1,%2,%3};"
        : "+f"(c[0]), "+f"(c[1]), "+f"(c[2]), "+f"(c[3])
        : "r"(a[0]), "r"(a[1]), "r"(a[2]), "r"(a[3]), "r"(b[0]), "r"(b[1]));
}

// 2-way bf16 split (hi exact-rounded, mid = residual)
__device__ __forceinline__ void split2(float v, unsigned short& h, unsigned short& m) {
    __nv_bfloat16 bh = __float2bfloat16(v);
    float r1 = v - __bfloat162float(bh);
    __nv_bfloat16 bm = __float2bfloat16(r1);
    h = __bfloat16_as_ushort(bh);
    m = __bfloat16_as_ushort(bm);
}

// ---------------- K1: LayerNorm + segment mean -> bf16 splits -------------------
__global__ void k_ln_seg(const float* __restrict__ vis,
                         const float* __restrict__ gamma,
                         const float* __restrict__ beta) {
    int seg = blockIdx.x;
    int t = threadIdx.x;
    int lane = t & 31, w = t >> 5;

    __shared__ float rs[PPT][8], rq[PPT][8];
    __shared__ float s_mu[PPT], s_ri[PPT];

    const float* base = vis + (size_t)seg * PPT * DV;
    float4 x[PPT];
    float s[PPT], q[PPT];
    #pragma unroll
    for (int p = 0; p < PPT; p++) {
        x[p] = *(const float4*)(base + (size_t)p * DV + 4 * t);
        s[p] = x[p].x + x[p].y + x[p].z + x[p].w;
        q[p] = x[p].x * x[p].x + x[p].y * x[p].y + x[p].z * x[p].z + x[p].w * x[p].w;
    }
    #pragma unroll
    for (int p = 0; p < PPT; p++) {
        #pragma unroll
        for (int o = 16; o > 0; o >>= 1) {
            s[p] += __shfl_down_sync(0xffffffffu, s[p], o);
            q[p] += __shfl_down_sync(0xffffffffu, q[p], o);
        }
        if (lane == 0) { rs[p][w] = s[p]; rq[p][w] = q[p]; }
    }
    __syncthreads();
    if (t < PPT) {
        float ss = 0.f, qq = 0.f;
        #pragma unroll
        for (int i = 0; i < 8; i++) { ss += rs[t][i]; qq += rq[t][i]; }
        float mu = ss * (1.0f / DV);
        float var = qq * (1.0f / DV) - mu * mu;
        s_mu[t] = mu;
        s_ri[t] = rsqrtf(var + 1e-5f);
    }
    __syncthreads();

    float4 g4 = *(const float4*)(gamma + 4 * t);
    float4 b4 = *(const float4*)(beta + 4 * t);
    float a0 = 0.f, a1 = 0.f, a2 = 0.f, a3 = 0.f;
    #pragma unroll
    for (int p = 0; p < PPT; p++) {
        float mu = s_mu[p], ri = s_ri[p];
        a0 += (x[p].x - mu) * ri * g4.x + b4.x;
        a1 += (x[p].y - mu) * ri * g4.y + b4.y;
        a2 += (x[p].z - mu) * ri * g4.z + b4.z;
        a3 += (x[p].w - mu) * ri * g4.w + b4.w;
    }
    float v[4] = { a0 * (1.0f / PPT), a1 * (1.0f / PPT), a2 * (1.0f / PPT), a3 * (1.0f / PPT) };
    unsigned short h[4], m[4];
    #pragma unroll
    for (int i = 0; i < 4; i++) split2(v[i], h[i], m[i]);
    size_t off = (size_t)seg * DV + 4 * t;
    uint2 ph = make_uint2((unsigned)h[0] | ((unsigned)h[1] << 16), (unsigned)h[2] | ((unsigned)h[3] << 16));
    uint2 pm = make_uint2((unsigned)m[0] | ((unsigned)m[1] << 16), (unsigned)m[2] | ((unsigned)m[3] << 16));
    *(uint2*)(g_Ah + off) = ph;
    *(uint2*)(g_Am + off) = pm;
}

// ---------------- K1b: transpose + split W [1024,768] -> W^T splits [768,1024] --
__global__ void k_wsplit(const float* __restrict__ Wp) {
    __shared__ float tile[32][33];
    int k0 = blockIdx.x * 32;       // K block
    int n0 = blockIdx.y * 32;       // N block
    int tx = threadIdx.x & 31, ty = threadIdx.x >> 5;   // 32x8
    #pragma unroll
    for (int i = 0; i < 4; i++)
        tile[ty + 8 * i][tx] = Wp[(size_t)(k0 + ty + 8 * i) * DT + n0 + tx];
    __syncthreads();
    #pragma unroll
    for (int i = 0; i < 4; i++) {
        int n = n0 + ty + 8 * i;
        int k = k0 + tx;
        float v = tile[tx][ty + 8 * i];
        unsigned short h, m;
        split2(v, h, m);
        size_t off = (size_t)n * DV + k;
        g_Wh[off] = h; g_Wm[off] = m;
    }
}

// ---------------- K2: bf16 split GEMM on mma.sync + fused pooled epilogue ------
// C[2048,768] = A @ W^T + bias via 3 bf16 cross terms (hh, hm, mh).
// 128x96 tile, grid (16,8) = 128 CTAs = one wave. 256 threads, warp grid 4Mx2N
// (warp tile 32x48 = exactly one batch row's 32 segments).

#define KPAD 40
#define A_SPLIT_B (TM * KPAD * 2)      // 10240 B
#define B_SPLIT_B (TN * KPAD * 2)      // 7680 B
#define BUF_STRIDE (2 * A_SPLIT_B + 2 * B_SPLIT_B)   // 35840 B
#define GEMM_SMEM (2 * BUF_STRIDE)                   // 71680 B

__device__ __forceinline__ void load_chunk(unsigned base, int tileM, int tileN, int c, int t) {
    #pragma unroll
    for (int s = 0; s < 2; s++) {
        const unsigned short* gA = s ? g_Am : g_Ah;
        #pragma unroll
        for (int i = 0; i < 2; i++) {
            int idx = t + 256 * i;              // 512 uint4
            int row = idx >> 2, kq = idx & 3;
            cp16(base + s * A_SPLIT_B + row * (KPAD * 2) + kq * 16,
                 gA + (size_t)(tileM * TM + row) * DV + c * 32 + kq * 8);
        }
    }
    #pragma unroll
    for (int s = 0; s < 2; s++) {
        const unsigned short* gB = s ? g_Wm : g_Wh;
        #pragma unroll
        for (int i = 0; i < 2; i++) {
            int idx = t + 256 * i;              // 384 uint4
            if (idx < (TN * 32) / 8) {
                int row = idx >> 2, kq = idx & 3;
                cp16(base + 2 * A_SPLIT_B + s * B_SPLIT_B + row * (KPAD * 2) + kq * 16,
                     gB + (size_t)(tileN * TN + row) * DV + c * 32 + kq * 8);
            }
        }
    }
}

__global__ void __launch_bounds__(256, 1) k_gemm_tc(const float* __restrict__ bp) {
    extern __shared__ __align__(16) unsigned char smem[];
    unsigned sb = smem_u32(smem);
    int t = threadIdx.x;
    int wid = t >> 5, lane = t & 31;
    int tileM = blockIdx.x, tileN = blockIdx.y;
    int warpM = (wid & 3) * 32, warpN = (wid >> 2) * 48;
    int g = lane >> 2, t4 = lane & 3;
    int l7 = lane & 7, mat = lane >> 3;

    int aRow = (mat & 1) * 8 + l7;
    int aK   = (mat >> 1) * 8;
    int bRow = (mat >> 1) * 8 + l7;
    int bK   = (mat & 1) * 8;

    float acc[2][6][4];
    #pragma unroll
    for (int i = 0; i < 2; i++)
        #pragma unroll
        for (int j = 0; j < 6; j++)
            #pragma unroll
            for (int k = 0; k < 4; k++) acc[i][j][k] = 0.f;

    load_chunk(sb, tileM, tileN, 0, t);
    cp_commit();

    for (int c = 0; c < DV / 32; c++) {
        if (c < DV / 32 - 1) {
            load_chunk(sb + ((c + 1) & 1) * BUF_STRIDE, tileM, tileN, c + 1, t);
            cp_commit();
            cp_wait1();
        } else {
            cp_wait0();
        }
        __syncthreads();

        unsigned base = sb + (c & 1) * BUF_STRIDE;
        #pragma unroll
        for (int kk = 0; kk < 2; kk++) {
            unsigned af[2][2][4];
            #pragma unroll
            for (int s = 0; s < 2; s++)
                #pragma unroll
                for (int mt = 0; mt < 2; mt++)
                    ldsm4(af[s][mt], base + s * A_SPLIT_B +
                          ((warpM + mt * 16 + aRow) * KPAD + kk * 16 + aK) * 2);
            unsigned bf[2][6][2];
            #pragma unroll
            for (int s = 0; s < 2; s++)
                #pragma unroll
                for (int nt = 0; nt < 3; nt++) {
                    unsigned r[4];
                    ldsm4(r, base + 2 * A_SPLIT_B + s * B_SPLIT_B +
                          ((warpN + nt * 16 + bRow) * KPAD + kk * 16 + bK) * 2);
                    bf[s][nt * 2][0] = r[0]; bf[s][nt * 2][1] = r[1];
                    bf[s][nt * 2 + 1][0] = r[2]; bf[s][nt * 2 + 1][1] = r[3];
                }
            #pragma unroll
            for (int tm = 0; tm < 3; tm++) {
                const int sa = (tm == 2) ? 1 : 0;
                const int sbv = (tm == 1) ? 1 : 0;
                #pragma unroll
                for (int mt = 0; mt < 2; mt++)
                    #pragma unroll
                    for (int n = 0; n < 6; n++)
                        mma16816(acc[mt][n], af[sa][mt], bf[sbv][n]);
            }
        }
        __syncthreads();
    }

    // epilogue 1: store segm tile with bias
    #pragma unroll
    for (int mt = 0; mt < 2; mt++) {
        int row0 = tileM * TM + warpM + mt * 16 + g;
        #pragma unroll
        for (int n = 0; n < 6; n++) {
            int col = tileN * TN + warpN + n * 8 + t4 * 2;
            float b0 = bp[col], b1 = bp[col + 1];
            float2 v0 = make_float2(acc[mt][n][0] + b0, acc[mt][n][1] + b1);
            float2 v1 = make_float2(acc[mt][n][2] + b0, acc[mt][n][3] + b1);
            *(float2*)(g_segm + (size_t)row0 * DT + col) = v0;
            *(float2*)(g_segm + (size_t)(row0 + 8) * DT + col) = v1;
        }
    }

    // epilogue 2: pooled = mean over this warp's 32 segment rows (= one batch b)
    #pragma unroll
    for (int n = 0; n < 6; n++) {
        float s0 = acc[0][n][0] + acc[0][n][2] + acc[1][n][0] + acc[1][n][2];
        float s1 = acc[0][n][1] + acc[0][n][3] + acc[1][n][1] + acc[1][n][3];
        #pragma unroll
        for (int o = 4; o < 32; o <<= 1) {
            s0 += __shfl_xor_sync(0xffffffffu, s0, o);
            s1 += __shfl_xor_sync(0xffffffffu, s1, o);
        }
        if (g == 0) {
            int b = tileM * 4 + (wid & 3);
            int col = tileN * TN + warpN + n * 8 + t4 * 2;
            g_pooled[b * DT + col]     = s0 * (1.0f / NSEG) + bp[col];
            g_pooled[b * DT + col + 1] = s1 * (1.0f / NSEG) + bp[col + 1];
        }
    }
}

// ---------------- K3a: placeholder rank + compacted positions -------------------
__global__ void k_rank(const int* __restrict__ ids, const int* __restrict__ php) {
    int b = blockIdx.x;
    int lane = threadIdx.x;
    int ph = *php;
    const int* row = ids + b * SS;
    int* orow = g_rank + b * SS;
    int base = 0;
    unsigned below = (1u << lane) - 1u;
    #pragma unroll
    for (int c = 0; c < SS / 32; c++) {
        int s = c * 32 + lane;
        int id = row[s];
        unsigned m = __ballot_sync(0xffffffffu, id == ph);
        int r = base + __popc(m & below);
        orow[s] = (id == ph) ? r : -1;
        if (id == ph && r < NSEG) g_phpos[b * NSEG + r] = s;
        base += __popc(m);
    }
    if (lane == 0) g_phcnt[b] = (base < NSEG) ? base : NSEG;
}

// ---------------- K3b: wte gather (all non-placeholder rows) --------------------
__global__ void k_emb_wte(const int* __restrict__ ids, const float* __restrict__ wte,
                          float* __restrict__ out) {
    int base = blockIdx.x * 8;
    int tid = threadIdx.x;         // 192 threads x float4 = 768 floats/row
    const float4* src[8];
    bool skip[8];
    #pragma unroll
    for (int r = 0; r < 8; r++) {
        int bs = base + r;
        int rk = g_rank[bs];
        skip[r] = (rk >= 0 && rk < NSEG);
        src[r] = (const float4*)(wte + (size_t)ids[bs] * DT);
    }
    float4 v[8];
    #pragma unroll
    for (int r = 0; r < 8; r++) if (!skip[r]) v[r] = src[r][tid];
    #pragma unroll
    for (int r = 0; r < 8; r++)
        if (!skip[r]) *(float4*)(out + (size_t)(base + r) * DT + 4 * tid) = v[r];
}

// ---------------- K3c: placeholder rows <- segm (after GEMM) --------------------
__global__ void k_emb_ph(float* __restrict__ out) {
    int b = blockIdx.x >> 5;
    int r = blockIdx.x & 31;
    if (r >= g_phcnt[b]) return;
    int s = g_phpos[b * NSEG + r];
    const float4* src = (const float4*)(g_segm + (size_t)(b * NSEG + r) * DT);
    float4* dst = (float4*)(out + ((size_t)b * SS + s) * DT);
    dst[threadIdx.x] = src[threadIdx.x];
}

// ---------------- K4b: raw Gram matrix G = pooled @ pooled^T --------------------
__global__ void k_sim() {
    int i = blockIdx.x;
    int t = threadIdx.x;
    int w = t >> 5, lane = t & 31;
    const float* a = g_pooled + (size_t)i * DT;
    for (int j = w; j < BB; j += 8) {
        const float* bv = g_pooled + (size_t)j * DT;
        float d = 0.f;
        for (int k = lane; k < DT; k += 32) d += a[k] * bv[k];
        #pragma unroll
        for (int o = 16; o > 0; o >>= 1) d += __shfl_down_sync(0xffffffffu, d, o);
        if (lane == 0) g_sim[i * BB + j] = d;
    }
}

// ---------------- K4c: CE loss (normalize on the fly; symmetric) ----------------
__global__ void k_loss(float* __restrict__ out, int out_size) {
    int i = threadIdx.x;
    __shared__ float sh[2];
    float gii = g_sim[i * BB + i];
    float ri = rsqrtf(gii);
    float m = -1e30f;
    float sim[BB];
    for (int j = 0; j < BB; j++) {
        float gjj = g_sim[j * BB + j];
        float v = g_sim[i * BB + j] * ri * rsqrtf(gjj) * (1.0f / 0.07f);
        sim[j] = v;
        m = fmaxf(m, v);
    }
    float se = 0.f;
    for (int j = 0; j < BB; j++) se += expf(sim[j] - m);
    float lr = sim[i] - (m + logf(se));

    float v = lr;
    #pragma unroll
    for (int o = 16; o > 0; o >>= 1) v += __shfl_down_sync(0xffffffffu, v, o);
    int w = i >> 5;
    if ((i & 31) == 0) sh[w] = v;
    __syncthreads();
    if (i == 0) out[out_size - 1] = -(sh[0] + sh[1]) / (float)BB;
}

// ---------------- launch (fork/join: wte gather overlaps LN+GEMM) ---------------
extern "C" void kernel_launch(void* const* d_in, const int* in_sizes, int n_in,
                              void* d_out, int out_size) {
    const float* vis   = (const float*)d_in[0];
    const float* gamma = (const float*)d_in[1];
    const float* beta  = (const float*)d_in[2];
    const float* Wp    = (const float*)d_in[3];
    const float* bp    = (const float*)d_in[4];
    const float* wte   = (const float*)d_in[5];
    const int*   ids   = (const int*)d_in[6];
    const int*   php   = (const int*)d_in[7];
    float* out = (float*)d_out;

    static int inited = 0;
    static cudaStream_t s1;
    static cudaEvent_t e0, e_rank, e1;
    if (!inited) {
        cudaFuncSetAttribute(k_gemm_tc, cudaFuncAttributeMaxDynamicSharedMemorySize, GEMM_SMEM);
        cudaStreamCreateWithFlags(&s1, cudaStreamNonBlocking);
        cudaEventCreateWithFlags(&e0, cudaEventDisableTiming);
        cudaEventCreateWithFlags(&e_rank, cudaEventDisableTiming);
        cudaEventCreateWithFlags(&e1, cudaEventDisableTiming);
        inited = 1;
    }

    // fork side stream
    cudaEventRecord(e0, 0);
    cudaStreamWaitEvent(s1, e0, 0);

    // side branch: rank -> wte gather (DRAM-bound, overlaps LN+GEMM)
    k_rank<<<BB, 32, 0, s1>>>(ids, php);
    cudaEventRecord(e_rank, s1);
    k_emb_wte<<<(BB * SS) / 8, 192, 0, s1>>>(ids, wte, out);
    cudaEventRecord(e1, s1);

    // main branch: LN -> W split -> GEMM(+pooled) -> placeholder rows -> sim -> loss
    k_ln_seg<<<BB * NSEG, 256>>>(vis, gamma, beta);
    k_wsplit<<<dim3(DV / 32, DT / 32), 256>>>(Wp);
    k_gemm_tc<<<dim3(MROWS / TM, DT / TN), 256, GEMM_SMEM>>>(bp);
    cudaStreamWaitEvent(0, e_rank, 0);
    k_emb_ph<<<BB * NSEG, 192>>>(out);
    k_sim<<<BB, 256>>>();
    k_loss<<<1, 64>>>(out, out_size);

    // join
    cudaStreamWaitEvent(0, e1, 0);
}

// round 7
// speedup vs baseline: 2.5000x; 1.0808x over previous
#include <cuda_runtime.h>
#include <cuda_bf16.h>
#include <math.h>

#define BB   64
#define PP   256
#define DV   1024
#define DT   768
#define SS   512
#define NSEG 32
#define PPT  8

#define MROWS 2048            // = BB*NSEG
#define TM    128             // GEMM M tile
#define TN    96              // GEMM N tile

// ---------------- scratch (static device globals; no allocation) ----------------
__device__ unsigned short g_Ah[MROWS * DV];   // bf16 hi split of segment means (K-major)
__device__ unsigned short g_Am[MROWS * DV];   // bf16 mid split
__device__ unsigned short g_Wh[DT * DV];      // bf16 hi split of W^T  [N=768][K=1024]
__device__ unsigned short g_Wm[DT * DV];      // bf16 mid split
__device__ float g_pooled[BB * DT];           // pooled (un-normalized) [64,768]
__device__ int   g_rank[BB * SS];             // placeholder rank or -1
__device__ int   g_phpos[BB * NSEG];          // position of r-th placeholder in row b
__device__ int   g_phcnt[BB];                 // per-row placeholder count
__device__ float g_sim[BB * BB];              // raw Gram matrix

// ---------------- PTX helpers (baseline PTX only: sm_80-class ops) --------------
__device__ __forceinline__ unsigned smem_u32(const void* p) {
    unsigned a;
    asm("{ .reg .u64 t; cvta.to.shared.u64 t, %1; cvt.u32.u64 %0, t; }" : "=r"(a) : "l"(p));
    return a;
}
__device__ __forceinline__ void cp16(unsigned saddr, const void* gptr) {
    asm volatile("cp.async.cg.shared.global [%0], [%1], 16;" :: "r"(saddr), "l"(gptr) : "memory");
}
__device__ __forceinline__ void cp_commit() {
    asm volatile("cp.async.commit_group;" ::: "memory");
}
__device__ __forceinline__ void cp_wait1() {
    asm volatile("cp.async.wait_group 1;" ::: "memory");
}
__device__ __forceinline__ void cp_wait0() {
    asm volatile("cp.async.wait_group 0;" ::: "memory");
}
__device__ __forceinline__ void ldsm4(unsigned* r, unsigned addr) {
    asm volatile("ldmatrix.sync.aligned.m8n8.x4.shared.b16 {%0,%1,%2,%3}, [%4];"
                 : "=r"(r[0]), "=r"(r[1]), "=r"(r[2]), "=r"(r[3]) : "r"(addr));
}
__device__ __forceinline__ void mma16816(float* c, const unsigned* a, const unsigned* b) {
    asm volatile(
        "mma.sync.aligned.m16n8k16.row.col.f32.bf16.bf16.f32 "
        "{%0,%1,%2,%3}, {%4,%5,%6,%7}, {%8,%9}, {%0,%1,%2,%3};"
        : "+f"(c[0]), "+f"(c[1]), "+f"(c[2]), "+f"(c[3])
        : "r"(a[0]), "r"(a[1]), "r"(a[2]), "r"(a[3]), "r"(b[0]), "r"(b[1]));
}

// 2-way bf16 split (hi exact-rounded, mid = residual)
__device__ __forceinline__ void split2(float v, unsigned short& h, unsigned short& m) {
    __nv_bfloat16 bh = __float2bfloat16(v);
    float r1 = v - __bfloat162float(bh);
    __nv_bfloat16 bm = __float2bfloat16(r1);
    h = __bfloat16_as_ushort(bh);
    m = __bfloat16_as_ushort(bm);
}

// ---------------- K1: LayerNorm + segment mean -> bf16 splits -------------------
__global__ void k_ln_seg(const float* __restrict__ vis,
                         const float* __restrict__ gamma,
                         const float* __restrict__ beta) {
    int seg = blockIdx.x;
    int t = threadIdx.x;
    int lane = t & 31, w = t >> 5;

    __shared__ float rs[PPT][8], rq[PPT][8];
    __shared__ float s_mu[PPT], s_ri[PPT];

    const float* base = vis + (size_t)seg * PPT * DV;
    float4 x[PPT];
    float s[PPT], q[PPT];
    #pragma unroll
    for (int p = 0; p < PPT; p++) {
        x[p] = *(const float4*)(base + (size_t)p * DV + 4 * t);
        s[p] = x[p].x + x[p].y + x[p].z + x[p].w;
        q[p] = x[p].x * x[p].x + x[p].y * x[p].y + x[p].z * x[p].z + x[p].w * x[p].w;
    }
    #pragma unroll
    for (int p = 0; p < PPT; p++) {
        #pragma unroll
        for (int o = 16; o > 0; o >>= 1) {
            s[p] += __shfl_down_sync(0xffffffffu, s[p], o);
            q[p] += __shfl_down_sync(0xffffffffu, q[p], o);
        }
        if (lane == 0) { rs[p][w] = s[p]; rq[p][w] = q[p]; }
    }
    __syncthreads();
    if (t < PPT) {
        float ss = 0.f, qq = 0.f;
        #pragma unroll
        for (int i = 0; i < 8; i++) { ss += rs[t][i]; qq += rq[t][i]; }
        float mu = ss * (1.0f / DV);
        float var = qq * (1.0f / DV) - mu * mu;
        s_mu[t] = mu;
        s_ri[t] = rsqrtf(var + 1e-5f);
    }
    __syncthreads();

    float4 g4 = *(const float4*)(gamma + 4 * t);
    float4 b4 = *(const float4*)(beta + 4 * t);
    float a0 = 0.f, a1 = 0.f, a2 = 0.f, a3 = 0.f;
    #pragma unroll
    for (int p = 0; p < PPT; p++) {
        float mu = s_mu[p], ri = s_ri[p];
        a0 += (x[p].x - mu) * ri * g4.x + b4.x;
        a1 += (x[p].y - mu) * ri * g4.y + b4.y;
        a2 += (x[p].z - mu) * ri * g4.z + b4.z;
        a3 += (x[p].w - mu) * ri * g4.w + b4.w;
    }
    float v[4] = { a0 * (1.0f / PPT), a1 * (1.0f / PPT), a2 * (1.0f / PPT), a3 * (1.0f / PPT) };
    unsigned short h[4], m[4];
    #pragma unroll
    for (int i = 0; i < 4; i++) split2(v[i], h[i], m[i]);
    size_t off = (size_t)seg * DV + 4 * t;
    uint2 ph = make_uint2((unsigned)h[0] | ((unsigned)h[1] << 16), (unsigned)h[2] | ((unsigned)h[3] << 16));
    uint2 pm = make_uint2((unsigned)m[0] | ((unsigned)m[1] << 16), (unsigned)m[2] | ((unsigned)m[3] << 16));
    *(uint2*)(g_Ah + off) = ph;
    *(uint2*)(g_Am + off) = pm;
}

// ---------------- K1b: transpose + split W [1024,768] -> W^T splits [768,1024] --
__global__ void k_wsplit(const float* __restrict__ Wp) {
    __shared__ float tile[32][33];
    int k0 = blockIdx.x * 32;       // K block
    int n0 = blockIdx.y * 32;       // N block
    int tx = threadIdx.x & 31, ty = threadIdx.x >> 5;   // 32x8
    #pragma unroll
    for (int i = 0; i < 4; i++)
        tile[ty + 8 * i][tx] = Wp[(size_t)(k0 + ty + 8 * i) * DT + n0 + tx];
    __syncthreads();
    #pragma unroll
    for (int i = 0; i < 4; i++) {
        int n = n0 + ty + 8 * i;
        int k = k0 + tx;
        float v = tile[tx][ty + 8 * i];
        unsigned short h, m;
        split2(v, h, m);
        size_t off = (size_t)n * DV + k;
        g_Wh[off] = h; g_Wm[off] = m;
    }
}

// ---------------- K2: bf16 split GEMM; epilogue scatters to out + pooled --------
// C[2048,768] = A @ W^T + bias via 3 bf16 cross terms (hh, hm, mh).
// 128x96 tile, grid (16,8) = 128 CTAs = one wave. 256 threads, warp grid 4Mx2N
// (warp tile 32x48 = exactly one batch row's 32 segments).
// Epilogue writes each segment row DIRECTLY into out at its placeholder slot.

#define KPAD 40
#define A_SPLIT_B (TM * KPAD * 2)      // 10240 B
#define B_SPLIT_B (TN * KPAD * 2)      // 7680 B
#define BUF_STRIDE (2 * A_SPLIT_B + 2 * B_SPLIT_B)   // 35840 B
#define GEMM_SMEM (2 * BUF_STRIDE)                   // 71680 B

__device__ __forceinline__ void load_chunk(unsigned base, int tileM, int tileN, int c, int t) {
    #pragma unroll
    for (int s = 0; s < 2; s++) {
        const unsigned short* gA = s ? g_Am : g_Ah;
        #pragma unroll
        for (int i = 0; i < 2; i++) {
            int idx = t + 256 * i;              // 512 uint4
            int row = idx >> 2, kq = idx & 3;
            cp16(base + s * A_SPLIT_B + row * (KPAD * 2) + kq * 16,
                 gA + (size_t)(tileM * TM + row) * DV + c * 32 + kq * 8);
        }
    }
    #pragma unroll
    for (int s = 0; s < 2; s++) {
        const unsigned short* gB = s ? g_Wm : g_Wh;
        #pragma unroll
        for (int i = 0; i < 2; i++) {
            int idx = t + 256 * i;              // 384 uint4
            if (idx < (TN * 32) / 8) {
                int row = idx >> 2, kq = idx & 3;
                cp16(base + 2 * A_SPLIT_B + s * B_SPLIT_B + row * (KPAD * 2) + kq * 16,
                     gB + (size_t)(tileN * TN + row) * DV + c * 32 + kq * 8);
            }
        }
    }
}

__global__ void __launch_bounds__(256, 1) k_gemm_tc(const float* __restrict__ bp,
                                                    float* __restrict__ out) {
    extern __shared__ __align__(16) unsigned char smem[];
    unsigned sb = smem_u32(smem);
    int t = threadIdx.x;
    int wid = t >> 5, lane = t & 31;
    int tileM = blockIdx.x, tileN = blockIdx.y;
    int warpM = (wid & 3) * 32, warpN = (wid >> 2) * 48;
    int g = lane >> 2, t4 = lane & 3;
    int l7 = lane & 7, mat = lane >> 3;

    int aRow = (mat & 1) * 8 + l7;
    int aK   = (mat >> 1) * 8;
    int bRow = (mat >> 1) * 8 + l7;
    int bK   = (mat & 1) * 8;

    float acc[2][6][4];
    #pragma unroll
    for (int i = 0; i < 2; i++)
        #pragma unroll
        for (int j = 0; j < 6; j++)
            #pragma unroll
            for (int k = 0; k < 4; k++) acc[i][j][k] = 0.f;

    load_chunk(sb, tileM, tileN, 0, t);
    cp_commit();

    for (int c = 0; c < DV / 32; c++) {
        if (c < DV / 32 - 1) {
            load_chunk(sb + ((c + 1) & 1) * BUF_STRIDE, tileM, tileN, c + 1, t);
            cp_commit();
            cp_wait1();
        } else {
            cp_wait0();
        }
        __syncthreads();

        unsigned base = sb + (c & 1) * BUF_STRIDE;
        #pragma unroll
        for (int kk = 0; kk < 2; kk++) {
            unsigned af[2][2][4];
            #pragma unroll
            for (int s = 0; s < 2; s++)
                #pragma unroll
                for (int mt = 0; mt < 2; mt++)
                    ldsm4(af[s][mt], base + s * A_SPLIT_B +
                          ((warpM + mt * 16 + aRow) * KPAD + kk * 16 + aK) * 2);
            unsigned bf[2][6][2];
            #pragma unroll
            for (int s = 0; s < 2; s++)
                #pragma unroll
                for (int nt = 0; nt < 3; nt++) {
                    unsigned r[4];
                    ldsm4(r, base + 2 * A_SPLIT_B + s * B_SPLIT_B +
                          ((warpN + nt * 16 + bRow) * KPAD + kk * 16 + bK) * 2);
                    bf[s][nt * 2][0] = r[0]; bf[s][nt * 2][1] = r[1];
                    bf[s][nt * 2 + 1][0] = r[2]; bf[s][nt * 2 + 1][1] = r[3];
                }
            #pragma unroll
            for (int tm = 0; tm < 3; tm++) {
                const int sa = (tm == 2) ? 1 : 0;
                const int sbv = (tm == 1) ? 1 : 0;
                #pragma unroll
                for (int mt = 0; mt < 2; mt++)
                    #pragma unroll
                    for (int n = 0; n < 6; n++)
                        mma16816(acc[mt][n], af[sa][mt], bf[sbv][n]);
            }
        }
        __syncthreads();
    }

    // epilogue 1: scatter rows directly into out at their placeholder slots
    #pragma unroll
    for (int mt = 0; mt < 2; mt++) {
        #pragma unroll
        for (int half = 0; half < 2; half++) {
            int row = tileM * TM + warpM + mt * 16 + half * 8 + g;   // global segment row
            int b = row >> 5, r = row & 31;
            if (r < g_phcnt[b]) {
                int spos = g_phpos[b * NSEG + r];
                float* dst = out + ((size_t)b * SS + spos) * DT;
                #pragma unroll
                for (int n = 0; n < 6; n++) {
                    int col = tileN * TN + warpN + n * 8 + t4 * 2;
                    float2 v = make_float2(acc[mt][n][half * 2 + 0] + bp[col],
                                           acc[mt][n][half * 2 + 1] + bp[col + 1]);
                    *(float2*)(dst + col) = v;
                }
            }
        }
    }

    // epilogue 2: pooled = mean over this warp's 32 segment rows (= one batch b)
    #pragma unroll
    for (int n = 0; n < 6; n++) {
        float s0 = acc[0][n][0] + acc[0][n][2] + acc[1][n][0] + acc[1][n][2];
        float s1 = acc[0][n][1] + acc[0][n][3] + acc[1][n][1] + acc[1][n][3];
        #pragma unroll
        for (int o = 4; o < 32; o <<= 1) {
            s0 += __shfl_xor_sync(0xffffffffu, s0, o);
            s1 += __shfl_xor_sync(0xffffffffu, s1, o);
        }
        if (g == 0) {
            int b = tileM * 4 + (wid & 3);
            int col = tileN * TN + warpN + n * 8 + t4 * 2;
            g_pooled[b * DT + col]     = s0 * (1.0f / NSEG) + bp[col];
            g_pooled[b * DT + col + 1] = s1 * (1.0f / NSEG) + bp[col + 1];
        }
    }
}

// ---------------- K3a: placeholder rank + compacted positions -------------------
__global__ void k_rank(const int* __restrict__ ids, const int* __restrict__ php) {
    int b = blockIdx.x;
    int lane = threadIdx.x;
    int ph = *php;
    const int* row = ids + b * SS;
    int* orow = g_rank + b * SS;
    int base = 0;
    unsigned below = (1u << lane) - 1u;
    #pragma unroll
    for (int c = 0; c < SS / 32; c++) {
        int s = c * 32 + lane;
        int id = row[s];
        unsigned m = __ballot_sync(0xffffffffu, id == ph);
        int r = base + __popc(m & below);
        orow[s] = (id == ph) ? r : -1;
        if (id == ph && r < NSEG) g_phpos[b * NSEG + r] = s;
        base += __popc(m);
    }
    if (lane == 0) g_phcnt[b] = (base < NSEG) ? base : NSEG;
}

// ---------------- K3b: wte gather (all non-placeholder rows) --------------------
__global__ void k_emb_wte(const int* __restrict__ ids, const float* __restrict__ wte,
                          float* __restrict__ out) {
    int base = blockIdx.x * 8;
    int tid = threadIdx.x;         // 192 threads x float4 = 768 floats/row
    const float4* src[8];
    bool skip[8];
    #pragma unroll
    for (int r = 0; r < 8; r++) {
        int bs = base + r;
        int rk = g_rank[bs];
        skip[r] = (rk >= 0 && rk < NSEG);
        src[r] = (const float4*)(wte + (size_t)ids[bs] * DT);
    }
    float4 v[8];
    #pragma unroll
    for (int r = 0; r < 8; r++) if (!skip[r]) v[r] = src[r][tid];
    #pragma unroll
    for (int r = 0; r < 8; r++)
        if (!skip[r]) *(float4*)(out + (size_t)(base + r) * DT + 4 * tid) = v[r];
}

// ---------------- K4b: raw Gram matrix G = pooled @ pooled^T --------------------
__global__ void k_sim() {
    int i = blockIdx.x;
    int t = threadIdx.x;
    int w = t >> 5, lane = t & 31;
    const float* a = g_pooled + (size_t)i * DT;
    for (int j = w; j < BB; j += 8) {
        const float* bv = g_pooled + (size_t)j * DT;
        float d = 0.f;
        for (int k = lane; k < DT; k += 32) d += a[k] * bv[k];
        #pragma unroll
        for (int o = 16; o > 0; o >>= 1) d += __shfl_down_sync(0xffffffffu, d, o);
        if (lane == 0) g_sim[i * BB + j] = d;
    }
}

// ---------------- K4c: CE loss (normalize on the fly; symmetric) ----------------
__global__ void k_loss(float* __restrict__ out, int out_size) {
    int i = threadIdx.x;
    __shared__ float sh[2];
    float gii = g_sim[i * BB + i];
    float ri = rsqrtf(gii);
    float m = -1e30f;
    float sim[BB];
    for (int j = 0; j < BB; j++) {
        float gjj = g_sim[j * BB + j];
        float v = g_sim[i * BB + j] * ri * rsqrtf(gjj) * (1.0f / 0.07f);
        sim[j] = v;
        m = fmaxf(m, v);
    }
    float se = 0.f;
    for (int j = 0; j < BB; j++) se += expf(sim[j] - m);
    float lr = sim[i] - (m + logf(se));

    float v = lr;
    #pragma unroll
    for (int o = 16; o > 0; o >>= 1) v += __shfl_down_sync(0xffffffffu, v, o);
    int w = i >> 5;
    if ((i & 31) == 0) sh[w] = v;
    __syncthreads();
    if (i == 0) out[out_size - 1] = -(sh[0] + sh[1]) / (float)BB;
}

// ---------------- launch (fork/join; wsplit+rank+wte on side stream) ------------
extern "C" void kernel_launch(void* const* d_in, const int* in_sizes, int n_in,
                              void* d_out, int out_size) {
    const float* vis   = (const float*)d_in[0];
    const float* gamma = (const float*)d_in[1];
    const float* beta  = (const float*)d_in[2];
    const float* Wp    = (const float*)d_in[3];
    const float* bp    = (const float*)d_in[4];
    const float* wte   = (const float*)d_in[5];
    const int*   ids   = (const int*)d_in[6];
    const int*   php   = (const int*)d_in[7];
    float* out = (float*)d_out;

    static int inited = 0;
    static cudaStream_t s1;
    static cudaEvent_t e0, e_pre, e1;
    if (!inited) {
        cudaFuncSetAttribute(k_gemm_tc, cudaFuncAttributeMaxDynamicSharedMemorySize, GEMM_SMEM);
        cudaStreamCreateWithFlags(&s1, cudaStreamNonBlocking);
        cudaEventCreateWithFlags(&e0, cudaEventDisableTiming);
        cudaEventCreateWithFlags(&e_pre, cudaEventDisableTiming);
        cudaEventCreateWithFlags(&e1, cudaEventDisableTiming);
        inited = 1;
    }

    // fork side stream
    cudaEventRecord(e0, 0);
    cudaStreamWaitEvent(s1, e0, 0);

    // side branch: rank -> W split (both GEMM prerequisites) -> wte gather
    k_rank<<<BB, 32, 0, s1>>>(ids, php);
    k_wsplit<<<dim3(DV / 32, DT / 32), 256, 0, s1>>>(Wp);
    cudaEventRecord(e_pre, s1);
    k_emb_wte<<<(BB * SS) / 8, 192, 0, s1>>>(ids, wte, out);
    cudaEventRecord(e1, s1);

    // main branch: LN -> GEMM (scatters placeholder rows + pooled) -> sim -> loss
    k_ln_seg<<<BB * NSEG, 256>>>(vis, gamma, beta);
    cudaStreamWaitEvent(0, e_pre, 0);
    k_gemm_tc<<<dim3(MROWS / TM, DT / TN), 256, GEMM_SMEM>>>(bp, out);
    k_sim<<<BB, 256>>>();
    k_loss<<<1, 64>>>(out, out_size);

    // join
    cudaStreamWaitEvent(0, e1, 0);
}